// round 1
// baseline (speedup 1.0000x reference)
#include <cuda_runtime.h>

#define Bz 4
#define C_IN 32
#define HH 64
#define WW 64
#define NPIX 4096                   // 64*64
#define NODES_PER_B (NPIX * C_IN)   // 131072
#define NODES_TOTAL (Bz * NODES_PER_B) // 524288
#define ADJ_PER_B ((long)NPIX * NPIX)  // 16777216
#define EPSV 1e-6f

// scratch (alloc-free rule: __device__ globals)
__device__ float g_S[Bz * NPIX];
__device__ float g_xv[Bz * NPIX];

#define POOL_BLOCKS 64
#define ZERO_BLOCKS 4032

// Blocks [0,64): compute channel-summed 4x4 avg pool (g_S) and patch certainty (g_xv).
// Blocks [64, 64+ZERO_BLOCKS): zero the 256MB adj region of the output.
__global__ __launch_bounds__(256) void fused_pool_zero(
    const float* __restrict__ x_feat,
    const float* __restrict__ x_var,
    float* __restrict__ out)
{
    int blk = blockIdx.x;
    if (blk < POOL_BLOCKS) {
        int g   = blk * 256 + threadIdx.x;   // 0..16383  -> (b, pixel)
        int b   = g >> 12;
        int pix = g & 4095;
        int R   = pix >> 6;
        int Cc  = pix & 63;

        const float4* xf4 = (const float4*)x_feat;
        float s = 0.f;
        for (int c = 0; c < C_IN; ++c) {
            #pragma unroll
            for (int i = 0; i < 4; ++i) {
                // row (R*4+i) of channel c, 4 contiguous cols starting at Cc*4 => one float4
                float4 v = xf4[(((b * C_IN + c) * 256 + (R * 4 + i)) << 6) + Cc];
                s += v.x + v.y + v.z + v.w;
            }
        }
        g_S[g] = s * (1.f / 16.f);

        const float4* xv4 = (const float4*)x_var;
        float sv = 0.f;
        #pragma unroll
        for (int i = 0; i < 4; ++i) {
            float4 v = xv4[((b * 256 + (R * 4 + i)) << 6) + Cc];
            sv += v.x + v.y + v.z + v.w;
        }
        g_xv[g] = 1.f - sv * (1.f / 16.f);
    } else {
        // zero adjacency region: Bz * 4096 * 4096 floats = 16,777,216 float4
        float4* adj4 = (float4*)(out + NODES_TOTAL);
        long total4 = (Bz * ADJ_PER_B) / 4;
        long tid    = (long)(blk - POOL_BLOCKS) * 256 + threadIdx.x;
        long stride = (long)ZERO_BLOCKS * 256;
        float4 z = make_float4(0.f, 0.f, 0.f, 0.f);
        for (long i = tid; i < total4; i += stride)
            adj4[i] = z;
    }
}

// One thread per (b, t): write tiled nodes + up to 4 sparse adj entries.
__global__ __launch_bounds__(256) void scatter_kernel(float* __restrict__ out)
{
    int g = blockIdx.x * 256 + threadIdx.x;   // 0..16383
    int b = g >> 12;
    int t = g & 4095;
    int R  = t >> 6;
    int Cc = t & 63;

    // nodes[b, i, j] = S[b, (i*32+j) mod 4096]  => flat[b, k] = S[b, k & 4095]
    float s = g_S[g];
    float* nodes = out + (long)b * NODES_PER_B;
    #pragma unroll
    for (int j = 0; j < 32; ++j)
        nodes[j * NPIX + t] = s;   // coalesced across threads (t contiguous)

    float xvt = g_xv[g];
    float* adjb = out + NODES_TOTAL + (long)b * ADJ_PER_B;
    const int base = b << 12;

    if (R + 1 < HH) {  // (dr,dc)=(1,0)
        float w = g_xv[base + t + WW] - xvt;
        if (w > EPSV) adjb[(long)(t + WW) * NPIX + t] = w;
    }
    if (R - 1 >= 0) {  // (-1,0)
        float w = g_xv[base + t - WW] - xvt;
        if (w > EPSV) adjb[(long)(t - WW) * NPIX + t] = w;
    }
    if (Cc + 1 < WW) { // (0,1)
        float w = g_xv[base + t + 1] - xvt;
        if (w > EPSV) adjb[(long)(t + 1) * NPIX + t] = w;
    }
    if (Cc - 1 >= 0) { // (0,-1)
        float w = g_xv[base + t - 1] - xvt;
        if (w > EPSV) adjb[(long)(t - 1) * NPIX + t] = w;
    }
}

extern "C" void kernel_launch(void* const* d_in, const int* in_sizes, int n_in,
                              void* d_out, int out_size)
{
    const float* x_feat = (const float*)d_in[0];
    const float* x_var  = (const float*)d_in[1];
    float* out = (float*)d_out;

    fused_pool_zero<<<POOL_BLOCKS + ZERO_BLOCKS, 256>>>(x_feat, x_var, out);
    scatter_kernel<<<POOL_BLOCKS, 256>>>(out);
}

// round 2
// speedup vs baseline: 1.0424x; 1.0424x over previous
#include <cuda_runtime.h>

#define Bz 4
#define C_IN 32
#define NPIX 4096                        // 64*64 pooled pixels
#define NODES_PER_B (NPIX * C_IN)        // 131072
#define NODES_TOTAL (Bz * NODES_PER_B)   // 524288
#define ADJ_PER_B   ((long)NPIX * NPIX)  // 16777216
#define ADJ4_PER_B  (ADJ_PER_B / 4)      // 4194304 float4 per batch
#define EPSV 1e-6f

// scratch (alloc-free rule: __device__ globals)
__device__ float g_xv[Bz * NPIX];

#define POOL_BLOCKS 64
#define ZERO_BLOCKS 4032

// K1: pool x_var -> patch certainty g_xv (tiny; 1 MB read)
__global__ __launch_bounds__(256) void pool_var_kernel(const float* __restrict__ x_var)
{
    int g   = blockIdx.x * 256 + threadIdx.x;   // 0..16383 -> (b, pixel)
    int b   = g >> 12;
    int pix = g & 4095;
    int R   = pix >> 6;
    int Cc  = pix & 63;

    const float4* xv4 = (const float4*)x_var;
    float sv = 0.f;
    #pragma unroll
    for (int i = 0; i < 4; ++i) {
        float4 v = xv4[((b * 256 + (R * 4 + i)) << 6) + Cc];
        sv += v.x + v.y + v.z + v.w;
    }
    g_xv[g] = 1.f - sv * (1.f / 16.f);
}

// K2: blocks [0,64): x_feat channel-sum 4x4 pool -> write tiled nodes directly.
//     blocks [64,..): zero adj with edge weights substituted inline.
__global__ __launch_bounds__(256) void fused_main(
    const float* __restrict__ x_feat,
    float* __restrict__ out)
{
    int blk = blockIdx.x;
    if (blk < POOL_BLOCKS) {
        int g   = blk * 256 + threadIdx.x;   // (b, t)
        int b   = g >> 12;
        int t   = g & 4095;
        int R   = t >> 6;
        int Cc  = t & 63;

        const float4* xf4 = (const float4*)x_feat;
        float s = 0.f;
        for (int c = 0; c < C_IN; ++c) {
            #pragma unroll
            for (int i = 0; i < 4; ++i) {
                float4 v = xf4[(((b * C_IN + c) * 256 + (R * 4 + i)) << 6) + Cc];
                s += v.x + v.y + v.z + v.w;
            }
        }
        s *= (1.f / 16.f);

        // nodes flat[b, k] = S[b, k & 4095]; coalesced across t
        float* nodes = out + (long)b * NODES_PER_B;
        #pragma unroll
        for (int j = 0; j < 32; ++j)
            nodes[j * NPIX + t] = s;
    } else {
        float4* adj4 = (float4*)(out + NODES_TOTAL);
        const long total4 = (long)Bz * ADJ4_PER_B;
        long tid    = (long)(blk - POOL_BLOCKS) * 256 + threadIdx.x;
        long stride = (long)ZERO_BLOCKS * 256;

        for (long i = tid; i < total4; i += stride) {
            float4 z = make_float4(0.f, 0.f, 0.f, 0.f);
            int within = (int)(i & (ADJ4_PER_B - 1));     // float4 idx within batch
            int f      = within >> 10;                    // adj row (from node)
            int tstart = (within & 1023) << 2;            // first of 4 t columns

            // nonzero candidates have t in {f-64, f-1, f+1, f+64}
            if ((unsigned)(tstart - f + 67) <= 131u) {
                int b = (int)(i >> 22);
                const float* xv = g_xv + (b << 12);
                float xvf = xv[f];
                #pragma unroll
                for (int j = 0; j < 4; ++j) {
                    int t = tstart + j;
                    int d = f - t;
                    bool cand;
                    if (d == 64 || d == -64)  cand = true;
                    else if (d == 1)          cand = (f & 63) != 0;   // f = t+1, same row
                    else if (d == -1)         cand = (f & 63) != 63;  // f = t-1, same row
                    else                      cand = false;
                    if (cand) {
                        float w = xvf - xv[t];
                        if (w > EPSV) ((float*)&z)[j] = w;
                    }
                }
            }
            adj4[i] = z;
        }
    }
}

extern "C" void kernel_launch(void* const* d_in, const int* in_sizes, int n_in,
                              void* d_out, int out_size)
{
    const float* x_feat = (const float*)d_in[0];
    const float* x_var  = (const float*)d_in[1];
    float* out = (float*)d_out;

    pool_var_kernel<<<POOL_BLOCKS, 256>>>(x_var);
    fused_main<<<POOL_BLOCKS + ZERO_BLOCKS, 256>>>(x_feat, out);
}

// round 3
// speedup vs baseline: 1.0818x; 1.0378x over previous
#include <cuda_runtime.h>

#define Bz 4
#define C_IN 32
#define NPIX 4096                        // 64*64 pooled pixels
#define NODES_PER_B (NPIX * C_IN)        // 131072
#define NODES_TOTAL (Bz * NODES_PER_B)   // 524288
#define ADJ_PER_B   ((long)NPIX * NPIX)  // 16777216 floats
#define EPSV 1e-6f

#define POOL_BLOCKS 64
#define TILE_FLOATS 16384                // 64KB tile = 4 adj rows
#define TILES_PER_B 1024                 // ADJ_PER_B / TILE_FLOATS
#define ZERO_BLOCKS (Bz * TILES_PER_B)   // 4096

// patch certainty for pooled pixel p of batch b, computed from x_var (L2-resident)
__device__ __forceinline__ float certainty(const float4* __restrict__ xv4, int b, int p)
{
    int R = p >> 6, C = p & 63;
    float s = 0.f;
    #pragma unroll
    for (int i = 0; i < 4; ++i) {
        float4 v = xv4[((b * 256 + (R * 4 + i)) << 6) + C];
        s += v.x + v.y + v.z + v.w;
    }
    return 1.f - s * (1.f / 16.f);
}

__global__ __launch_bounds__(256) void fused_all(
    const float* __restrict__ x_feat,
    const float* __restrict__ x_var,
    float* __restrict__ out)
{
    int blk = blockIdx.x;
    int tid = threadIdx.x;

    if (blk < POOL_BLOCKS) {
        // ---- nodes: channel-summed 4x4 pool of x_feat, tiled 32x ----
        int g   = blk * 256 + tid;       // (b, t)
        int b   = g >> 12;
        int t   = g & 4095;
        int R   = t >> 6;
        int Cc  = t & 63;

        const float4* xf4 = (const float4*)x_feat;
        float s = 0.f;
        for (int c = 0; c < C_IN; ++c) {
            #pragma unroll
            for (int i = 0; i < 4; ++i) {
                float4 v = xf4[(((b * C_IN + c) * 256 + (R * 4 + i)) << 6) + Cc];
                s += v.x + v.y + v.z + v.w;
            }
        }
        s *= (1.f / 16.f);

        float* nodes = out + (long)b * NODES_PER_B;
        #pragma unroll
        for (int j = 0; j < 32; ++j)
            nodes[j * NPIX + t] = s;     // coalesced across t
        return;
    }

    // ---- adjacency tile: one 64KB tile (4 rows) per block ----
    int tile = blk - POOL_BLOCKS;        // 0..4095
    int b    = tile >> 10;               // batch
    int f0   = (tile & 1023) << 2;       // first adj row of this tile

    float* adjb  = out + NODES_TOTAL + (long)b * ADJ_PER_B;
    float4* dst4 = (float4*)(adjb + (long)f0 * NPIX) + tid;

    // Phase a: stream 64KB of zeros; 16 unrolled STG.128 off one base.
    const float4 z = make_float4(0.f, 0.f, 0.f, 0.f);
    #pragma unroll
    for (int k = 0; k < 16; ++k)
        dst4[k * 256] = z;

    __syncthreads();   // orders the zeros before the patch stores below

    // Phase b: patch at most 16 candidate edges (4 rows x 4 neighbors).
    if (tid < 16) {
        int f   = f0 + (tid >> 2);
        int sel = tid & 3;
        int t; bool valid;
        if      (sel == 0) { t = f - 64; valid = (f >= 64);        }
        else if (sel == 1) { t = f + 64; valid = (f < NPIX - 64);  }
        else if (sel == 2) { t = f - 1;  valid = ((f & 63) != 0);  }
        else               { t = f + 1;  valid = ((f & 63) != 63); }
        if (valid) {
            const float4* xv4 = (const float4*)x_var;
            float w = certainty(xv4, b, f) - certainty(xv4, b, t);
            if (w > EPSV)
                adjb[(long)f * NPIX + t] = w;
        }
    }
}

extern "C" void kernel_launch(void* const* d_in, const int* in_sizes, int n_in,
                              void* d_out, int out_size)
{
    const float* x_feat = (const float*)d_in[0];
    const float* x_var  = (const float*)d_in[1];
    float* out = (float*)d_out;

    fused_all<<<POOL_BLOCKS + ZERO_BLOCKS, 256>>>(x_feat, x_var, out);
}